// round 2
// baseline (speedup 1.0000x reference)
#include <cuda_runtime.h>
#include <cstdint>
#include <cstddef>

#define D 128
#define MAXN 100000
#define MAXE 1600000
#define BM 64
#define KSTRIDE 65   // u64 stride for smem tiles [128][KSTRIDE]

typedef unsigned long long u64;

// ---------------------------------------------------------------------------
// Device scratch (static; allocation-guard-safe)
// ---------------------------------------------------------------------------
__device__ float g_agg[(size_t)MAXN * D];        // 51.2 MB aggregated rows
__device__ u64   g_edges[MAXE];                  // 12.8 MB packed (w<<32 | src)
__device__ int   g_cnt[MAXN];                    // per-dst degree
__device__ int   g_row[MAXN + 1];                // CSR row starts
__device__ int   g_cur[MAXN];                    // scatter cursors

// ---------------------------------------------------------------------------
// packed f32x2 helpers (sm_103a)
// ---------------------------------------------------------------------------
__device__ __forceinline__ u64 dup2(float f) {
    u64 r; unsigned u = __float_as_uint(f);
    asm("mov.b64 %0, {%1, %1};" : "=l"(r) : "r"(u));
    return r;
}
__device__ __forceinline__ void ffma2(u64& d, u64 a, u64 b) {
    asm("fma.rn.f32x2 %0, %1, %2, %0;" : "+l"(d) : "l"(a), "l"(b));
}
__device__ __forceinline__ float2 unpack2(u64 v) {
    unsigned lo, hi;
    asm("mov.b64 {%0, %1}, %2;" : "=r"(lo), "=r"(hi) : "l"(v));
    float2 r; r.x = __uint_as_float(lo); r.y = __uint_as_float(hi);
    return r;
}

// int64-vs-int32 index dtype sniff (int64 indices < 100000 have zero hi words)
__device__ __forceinline__ bool detect64(const int* p) {
    unsigned o = 0;
    #pragma unroll
    for (int i = 0; i < 16; i++) o |= (unsigned)p[2 * i + 1];
    return o == 0u;
}

// ---------------------------------------------------------------------------
// CSR build: zero counts -> histogram -> scan -> scatter
// ---------------------------------------------------------------------------
__global__ void zero_cnt_kernel(int n) {
    int i = blockIdx.x * blockDim.x + threadIdx.x;
    if (i < n) g_cnt[i] = 0;
}

__global__ void hist_kernel(const int* __restrict__ dst_raw, int E) {
    const bool is64 = detect64(dst_raw);
    int e = blockIdx.x * blockDim.x + threadIdx.x;
    if (e >= E) return;
    int d = is64 ? (int)((const long long*)dst_raw)[e] : dst_raw[e];
    atomicAdd(&g_cnt[d], 1);
}

// single-block exclusive scan of g_cnt into g_row / g_cur
__global__ void __launch_bounds__(1024) scan_kernel(int n, int E) {
    __shared__ int ssum[1024];
    const int tid = threadIdx.x;
    const int chunk = (n + 1023) >> 10;
    const int beg = tid * chunk;
    const int end = min(beg + chunk, n);

    int s = 0;
    for (int i = beg; i < end; i++) s += g_cnt[i];
    ssum[tid] = s;
    __syncthreads();
    // Hillis-Steele inclusive scan
    for (int off = 1; off < 1024; off <<= 1) {
        int v = (tid >= off) ? ssum[tid - off] : 0;
        __syncthreads();
        ssum[tid] += v;
        __syncthreads();
    }
    int run = (tid > 0) ? ssum[tid - 1] : 0;
    for (int i = beg; i < end; i++) {
        int c = g_cnt[i];
        g_row[i] = run;
        g_cur[i] = run;
        run += c;
    }
    if (tid == 1023) g_row[n] = E;
}

__global__ void scatter_kernel(const int* __restrict__ src_raw,
                               const int* __restrict__ dst_raw,
                               const float* __restrict__ w, int E) {
    const bool is64 = detect64(src_raw);
    int e = blockIdx.x * blockDim.x + threadIdx.x;
    if (e >= E) return;
    int s, d;
    if (is64) {
        s = (int)((const long long*)src_raw)[e];
        d = (int)((const long long*)dst_raw)[e];
    } else {
        s = src_raw[e];
        d = dst_raw[e];
    }
    float ww = w[e];
    int pos = atomicAdd(&g_cur[d], 1);
    g_edges[pos] = ((u64)__float_as_uint(ww) << 32) | (unsigned)s;
}

// ---------------------------------------------------------------------------
// Aggregation: one warp per dst node, register accumulation, no float atomics.
// ---------------------------------------------------------------------------
__global__ void __launch_bounds__(256) agg_kernel(const float* __restrict__ x, int n) {
    const int warp = (blockIdx.x * blockDim.x + threadIdx.x) >> 5;
    if (warp >= n) return;
    const int lane = threadIdx.x & 31;

    const int beg = g_row[warp];
    const int end = g_row[warp + 1];
    const float4* x4 = (const float4*)x;

    float4 a0 = make_float4(0.f, 0.f, 0.f, 0.f);
    float4 a1 = make_float4(0.f, 0.f, 0.f, 0.f);

    int i = beg;
    for (; i + 1 < end; i += 2) {
        u64 e0 = g_edges[i];
        u64 e1 = g_edges[i + 1];
        int   s0 = (int)(unsigned)e0;
        int   s1 = (int)(unsigned)e1;
        float w0 = __uint_as_float((unsigned)(e0 >> 32));
        float w1 = __uint_as_float((unsigned)(e1 >> 32));
        float4 v0 = __ldg(&x4[(size_t)s0 * (D / 4) + lane]);
        float4 v1 = __ldg(&x4[(size_t)s1 * (D / 4) + lane]);
        a0.x += w0 * v0.x; a0.y += w0 * v0.y; a0.z += w0 * v0.z; a0.w += w0 * v0.w;
        a1.x += w1 * v1.x; a1.y += w1 * v1.y; a1.z += w1 * v1.z; a1.w += w1 * v1.w;
    }
    if (i < end) {
        u64 e0 = g_edges[i];
        int   s0 = (int)(unsigned)e0;
        float w0 = __uint_as_float((unsigned)(e0 >> 32));
        float4 v0 = __ldg(&x4[(size_t)s0 * (D / 4) + lane]);
        a0.x += w0 * v0.x; a0.y += w0 * v0.y; a0.z += w0 * v0.z; a0.w += w0 * v0.w;
    }
    float4 r = make_float4(a0.x + a1.x, a0.y + a1.y, a0.z + a1.z, a0.w + a1.w);
    ((float4*)g_agg)[(size_t)warp * (D / 4) + lane] = r;
}

// ---------------------------------------------------------------------------
// Fused dual GEMM:  out = agg @ W_nbrs + x @ W_self + bias  (f32x2 path)
// ---------------------------------------------------------------------------
__global__ void __launch_bounds__(256) gemm_kernel(
    const float* __restrict__ x,
    const float* __restrict__ Wn,
    const float* __restrict__ Ws,
    const float* __restrict__ bias,
    float* __restrict__ out,
    int n)
{
    extern __shared__ u64 sm[];
    u64* s_a = sm;
    u64* s_x = sm + 128 * KSTRIDE;

    const int tid = threadIdx.x;
    const int row0 = blockIdx.x * BM;

    for (int idx = tid; idx < BM * D; idx += 256) {
        int r = idx >> 7;
        int k = idx & 127;
        int gr = row0 + r;
        float av = 0.f, xv = 0.f;
        if (gr < n) {
            av = g_agg[(size_t)gr * D + k];
            xv = x[(size_t)gr * D + k];
        }
        s_a[k * KSTRIDE + r] = dup2(av);
        s_x[k * KSTRIDE + r] = dup2(xv);
    }
    __syncthreads();

    const int c0 = (tid & 15) * 8;
    const int r0 = (tid >> 4) * 4;

    u64 acc[4][4];
    #pragma unroll
    for (int r = 0; r < 4; r++)
        #pragma unroll
        for (int c = 0; c < 4; c++) acc[r][c] = 0ull;

    #pragma unroll 4
    for (int k = 0; k < 128; k++) {
        const ulonglong2* pn = (const ulonglong2*)(Wn + (size_t)k * D + c0);
        const ulonglong2* ps = (const ulonglong2*)(Ws + (size_t)k * D + c0);
        ulonglong2 n0 = __ldg(pn);
        ulonglong2 n1 = __ldg(pn + 1);
        ulonglong2 t0 = __ldg(ps);
        ulonglong2 t1 = __ldg(ps + 1);
        #pragma unroll
        for (int r = 0; r < 4; r++) {
            u64 a  = s_a[k * KSTRIDE + r0 + r];
            u64 xx = s_x[k * KSTRIDE + r0 + r];
            ffma2(acc[r][0], a, n0.x); ffma2(acc[r][0], xx, t0.x);
            ffma2(acc[r][1], a, n0.y); ffma2(acc[r][1], xx, t0.y);
            ffma2(acc[r][2], a, n1.x); ffma2(acc[r][2], xx, t1.x);
            ffma2(acc[r][3], a, n1.y); ffma2(acc[r][3], xx, t1.y);
        }
    }

    float4 b0 = *(const float4*)(bias + c0);
    float4 b1 = *(const float4*)(bias + c0 + 4);

    #pragma unroll
    for (int r = 0; r < 4; r++) {
        int row = row0 + r0 + r;
        if (row >= n) continue;
        float2 p0 = unpack2(acc[r][0]);
        float2 p1 = unpack2(acc[r][1]);
        float2 p2 = unpack2(acc[r][2]);
        float2 p3 = unpack2(acc[r][3]);
        float4 o0 = make_float4(p0.x + b0.x, p0.y + b0.y, p1.x + b0.z, p1.y + b0.w);
        float4 o1 = make_float4(p2.x + b1.x, p2.y + b1.y, p3.x + b1.z, p3.y + b1.w);
        float4* op = (float4*)(out + (size_t)row * D + c0);
        op[0] = o0;
        op[1] = o1;
    }
}

// ---------------------------------------------------------------------------
// launch
// ---------------------------------------------------------------------------
extern "C" void kernel_launch(void* const* d_in, const int* in_sizes, int n_in,
                              void* d_out, int out_size) {
    const float* x    = (const float*)d_in[0];
    const int*   src  = (const int*)d_in[1];
    const int*   dst  = (const int*)d_in[2];
    const float* w    = (const float*)d_in[3];
    const float* Wn   = (const float*)d_in[4];
    const float* Ws   = (const float*)d_in[5];
    const float* bias = (const float*)d_in[6];
    float* out = (float*)d_out;

    const int n = in_sizes[0] / D;   // nodes
    const int E = in_sizes[3];       // edges (weight count is dtype-independent)
    const int blk = 256;

    zero_cnt_kernel<<<(n + blk - 1) / blk, blk>>>(n);
    hist_kernel<<<(E + blk - 1) / blk, blk>>>(dst, E);
    scan_kernel<<<1, 1024>>>(n, E);
    scatter_kernel<<<(E + blk - 1) / blk, blk>>>(src, dst, w, E);

    {   // aggregation: one warp per node
        int warps_per_blk = blk / 32;
        int grid = (n + warps_per_blk - 1) / warps_per_blk;
        agg_kernel<<<grid, blk>>>(x, n);
    }

    {   // fused dual GEMM epilogue
        size_t smem = 2ull * 128 * KSTRIDE * sizeof(u64);  // 133,120 B
        cudaFuncSetAttribute(gemm_kernel,
                             cudaFuncAttributeMaxDynamicSharedMemorySize,
                             (int)smem);
        int grid = (n + BM - 1) / BM;
        gemm_kernel<<<grid, 256, smem>>>(x, Wn, Ws, bias, out, n);
    }
}

// round 3
// speedup vs baseline: 1.3412x; 1.3412x over previous
#include <cuda_runtime.h>
#include <cstdint>
#include <cstddef>

#define D 128
#define MAXN 100000
#define MAXE 1600000
#define BM 64
#define RSTR 66          // float stride for smem tiles [128][RSTR]

typedef unsigned long long u64;

// ---------------------------------------------------------------------------
// Device scratch (static; allocation-guard-safe)
// ---------------------------------------------------------------------------
__device__ float g_agg[(size_t)MAXN * D];        // 51.2 MB aggregated rows
__device__ u64   g_edges[MAXE];                  // 12.8 MB packed (w<<32 | src)
__device__ int   g_cnt[MAXN];                    // per-dst degree
__device__ int   g_row[MAXN + 1];                // CSR row starts
__device__ int   g_cur[MAXN];                    // scatter cursors
__device__ int   g_is64;                         // index dtype flag

// ---------------------------------------------------------------------------
// packed f32x2 helpers (sm_103a)
// ---------------------------------------------------------------------------
__device__ __forceinline__ u64 dup2(float f) {
    u64 r; unsigned u = __float_as_uint(f);
    asm("mov.b64 %0, {%1, %1};" : "=l"(r) : "r"(u));
    return r;
}
__device__ __forceinline__ void ffma2(u64& d, u64 a, u64 b) {
    asm("fma.rn.f32x2 %0, %1, %2, %0;" : "+l"(d) : "l"(a), "l"(b));
}
__device__ __forceinline__ float2 unpack2(u64 v) {
    unsigned lo, hi;
    asm("mov.b64 {%0, %1}, %2;" : "=r"(lo), "=r"(hi) : "l"(v));
    float2 r; r.x = __uint_as_float(lo); r.y = __uint_as_float(hi);
    return r;
}

// ---------------------------------------------------------------------------
// Kernel 1: zero counters + sniff index dtype once
// (int64 indices < 100000 have all-zero high words)
// ---------------------------------------------------------------------------
__global__ void zero_cnt_kernel(const int* __restrict__ idx_raw, int n) {
    int i = blockIdx.x * blockDim.x + threadIdx.x;
    if (i < n) g_cnt[i] = 0;
    if (i == 0) {
        unsigned o = 0;
        #pragma unroll
        for (int j = 0; j < 16; j++) o |= (unsigned)idx_raw[2 * j + 1];
        g_is64 = (o == 0u) ? 1 : 0;
    }
}

// ---------------------------------------------------------------------------
// Kernel 2: histogram of destinations
// ---------------------------------------------------------------------------
__global__ void hist_kernel(const int* __restrict__ dst_raw, int E) {
    const bool is64 = (g_is64 != 0);
    int e = blockIdx.x * blockDim.x + threadIdx.x;
    if (e >= E) return;
    int d = is64 ? (int)((const long long*)dst_raw)[e] : dst_raw[e];
    atomicAdd(&g_cnt[d], 1);
}

// ---------------------------------------------------------------------------
// Kernel 3: single-block exclusive scan of g_cnt into g_row / g_cur
// ---------------------------------------------------------------------------
__global__ void __launch_bounds__(1024) scan_kernel(int n, int E) {
    __shared__ int ssum[1024];
    const int tid = threadIdx.x;
    const int chunk = (n + 1023) >> 10;
    const int beg = tid * chunk;
    const int end = min(beg + chunk, n);

    int s = 0;
    for (int i = beg; i < end; i++) s += g_cnt[i];
    ssum[tid] = s;
    __syncthreads();
    for (int off = 1; off < 1024; off <<= 1) {
        int v = (tid >= off) ? ssum[tid - off] : 0;
        __syncthreads();
        ssum[tid] += v;
        __syncthreads();
    }
    int run = (tid > 0) ? ssum[tid - 1] : 0;
    for (int i = beg; i < end; i++) {
        int c = g_cnt[i];
        g_row[i] = run;
        g_cur[i] = run;
        run += c;
    }
    if (tid == 1023) g_row[n] = E;
}

// ---------------------------------------------------------------------------
// Kernel 4: scatter packed (w,src) records into CSR order (2 edges/thread)
// ---------------------------------------------------------------------------
__global__ void scatter_kernel(const int* __restrict__ src_raw,
                               const int* __restrict__ dst_raw,
                               const float* __restrict__ w, int E) {
    const bool is64 = (g_is64 != 0);
    int t = blockIdx.x * blockDim.x + threadIdx.x;
    int e = t * 2;
    if (e >= E) return;
    int cnt = min(2, E - e);
    #pragma unroll
    for (int j = 0; j < 2; j++) {
        if (j >= cnt) break;
        int s, d;
        if (is64) {
            s = (int)((const long long*)src_raw)[e + j];
            d = (int)((const long long*)dst_raw)[e + j];
        } else {
            s = src_raw[e + j];
            d = dst_raw[e + j];
        }
        float ww = w[e + j];
        int pos = atomicAdd(&g_cur[d], 1);
        g_edges[pos] = ((u64)__float_as_uint(ww) << 32) | (unsigned)s;
    }
}

// ---------------------------------------------------------------------------
// Kernel 5: aggregation — one warp per dst node, 4-deep MLP, no float atomics
// ---------------------------------------------------------------------------
__global__ void __launch_bounds__(256) agg_kernel(const float* __restrict__ x, int n) {
    const int warp = (blockIdx.x * blockDim.x + threadIdx.x) >> 5;
    if (warp >= n) return;
    const int lane = threadIdx.x & 31;

    const int beg = g_row[warp];
    const int end = g_row[warp + 1];
    const float4* x4 = (const float4*)x;

    float4 a0 = make_float4(0.f, 0.f, 0.f, 0.f);
    float4 a1 = make_float4(0.f, 0.f, 0.f, 0.f);
    float4 a2 = make_float4(0.f, 0.f, 0.f, 0.f);
    float4 a3 = make_float4(0.f, 0.f, 0.f, 0.f);

    int i = beg;
    for (; i + 3 < end; i += 4) {
        u64 e0 = g_edges[i];
        u64 e1 = g_edges[i + 1];
        u64 e2 = g_edges[i + 2];
        u64 e3 = g_edges[i + 3];
        float4 v0 = __ldg(&x4[(size_t)(unsigned)e0 * (D / 4) + lane]);
        float4 v1 = __ldg(&x4[(size_t)(unsigned)e1 * (D / 4) + lane]);
        float4 v2 = __ldg(&x4[(size_t)(unsigned)e2 * (D / 4) + lane]);
        float4 v3 = __ldg(&x4[(size_t)(unsigned)e3 * (D / 4) + lane]);
        float w0 = __uint_as_float((unsigned)(e0 >> 32));
        float w1 = __uint_as_float((unsigned)(e1 >> 32));
        float w2 = __uint_as_float((unsigned)(e2 >> 32));
        float w3 = __uint_as_float((unsigned)(e3 >> 32));
        a0.x += w0 * v0.x; a0.y += w0 * v0.y; a0.z += w0 * v0.z; a0.w += w0 * v0.w;
        a1.x += w1 * v1.x; a1.y += w1 * v1.y; a1.z += w1 * v1.z; a1.w += w1 * v1.w;
        a2.x += w2 * v2.x; a2.y += w2 * v2.y; a2.z += w2 * v2.z; a2.w += w2 * v2.w;
        a3.x += w3 * v3.x; a3.y += w3 * v3.y; a3.z += w3 * v3.w * 0.f + w3 * v3.z; a3.w += w3 * v3.w;
    }
    for (; i < end; i++) {
        u64 e0 = g_edges[i];
        float w0 = __uint_as_float((unsigned)(e0 >> 32));
        float4 v0 = __ldg(&x4[(size_t)(unsigned)e0 * (D / 4) + lane]);
        a0.x += w0 * v0.x; a0.y += w0 * v0.y; a0.z += w0 * v0.z; a0.w += w0 * v0.w;
    }
    float4 r;
    r.x = (a0.x + a1.x) + (a2.x + a3.x);
    r.y = (a0.y + a1.y) + (a2.y + a3.y);
    r.z = (a0.z + a1.z) + (a2.z + a3.z);
    r.w = (a0.w + a1.w) + (a2.w + a3.w);
    ((float4*)g_agg)[(size_t)warp * (D / 4) + lane] = r;
}

// ---------------------------------------------------------------------------
// Kernel 6: fused dual GEMM  out = agg @ Wn + x @ Ws + bias
// Row-pair f32x2 packing: acc u64 = {out[r], out[r+1]}. Smem tiles are plain
// floats in [k][row] layout; LDS.64 fetches a row pair directly. Only the 16
// weight scalars per k get duplicated (alu-pipe MOVs, hidden under FFMA).
// Smem 67.5 KB -> 2 blocks/SM.
// ---------------------------------------------------------------------------
__global__ void __launch_bounds__(256, 2) gemm_kernel(
    const float* __restrict__ x,
    const float* __restrict__ Wn,
    const float* __restrict__ Ws,
    const float* __restrict__ bias,
    float* __restrict__ out,
    int n)
{
    extern __shared__ float sm[];
    float* s_a = sm;                  // [128][RSTR]
    float* s_x = sm + 128 * RSTR;

    const int tid = threadIdx.x;
    const int row0 = blockIdx.x * BM;

    for (int idx = tid; idx < BM * D; idx += 256) {
        int r = idx >> 7;            // 0..63
        int k = idx & 127;
        int gr = row0 + r;
        float av = 0.f, xv = 0.f;
        if (gr < n) {
            av = g_agg[(size_t)gr * D + k];
            xv = x[(size_t)gr * D + k];
        }
        s_a[k * RSTR + r] = av;
        s_x[k * RSTR + r] = xv;
    }
    __syncthreads();

    const int c0 = (tid & 15) * 8;   // 16 col groups of 8
    const int r0 = (tid >> 4) * 4;   // 16 row groups of 4 (two row-pairs)

    u64 acc0[8], acc1[8];            // pair (r0,r0+1), pair (r0+2,r0+3)
    #pragma unroll
    for (int c = 0; c < 8; c++) { acc0[c] = 0ull; acc1[c] = 0ull; }

    #pragma unroll 4
    for (int k = 0; k < 128; k++) {
        u64 a01 = *(const u64*)(s_a + k * RSTR + r0);
        u64 a23 = *(const u64*)(s_a + k * RSTR + r0 + 2);
        u64 x01 = *(const u64*)(s_x + k * RSTR + r0);
        u64 x23 = *(const u64*)(s_x + k * RSTR + r0 + 2);
        float4 wn0 = __ldg((const float4*)(Wn + (size_t)k * D + c0));
        float4 wn1 = __ldg((const float4*)(Wn + (size_t)k * D + c0 + 4));
        float4 ws0 = __ldg((const float4*)(Ws + (size_t)k * D + c0));
        float4 ws1 = __ldg((const float4*)(Ws + (size_t)k * D + c0 + 4));
        const float wn[8] = {wn0.x, wn0.y, wn0.z, wn0.w, wn1.x, wn1.y, wn1.z, wn1.w};
        const float ws[8] = {ws0.x, ws0.y, ws0.z, ws0.w, ws1.x, ws1.y, ws1.z, ws1.w};
        #pragma unroll
        for (int c = 0; c < 8; c++) {
            u64 wnc = dup2(wn[c]);
            u64 wsc = dup2(ws[c]);
            ffma2(acc0[c], a01, wnc); ffma2(acc0[c], x01, wsc);
            ffma2(acc1[c], a23, wnc); ffma2(acc1[c], x23, wsc);
        }
    }

    float b[8];
    *(float4*)(b)     = *(const float4*)(bias + c0);
    *(float4*)(b + 4) = *(const float4*)(bias + c0 + 4);

    // rows r0 / r0+1 from acc0, rows r0+2 / r0+3 from acc1
    #pragma unroll
    for (int p = 0; p < 2; p++) {
        const u64* acc = p ? acc1 : acc0;
        float lo[8], hi[8];
        #pragma unroll
        for (int c = 0; c < 8; c++) {
            float2 v = unpack2(acc[c]);
            lo[c] = v.x + b[c];
            hi[c] = v.y + b[c];
        }
        int rlo = row0 + r0 + 2 * p;
        int rhi = rlo + 1;
        if (rlo < n) {
            float4* op = (float4*)(out + (size_t)rlo * D + c0);
            op[0] = make_float4(lo[0], lo[1], lo[2], lo[3]);
            op[1] = make_float4(lo[4], lo[5], lo[6], lo[7]);
        }
        if (rhi < n) {
            float4* op = (float4*)(out + (size_t)rhi * D + c0);
            op[0] = make_float4(hi[0], hi[1], hi[2], hi[3]);
            op[1] = make_float4(hi[4], hi[5], hi[6], hi[7]);
        }
    }
}

// ---------------------------------------------------------------------------
// launch
// ---------------------------------------------------------------------------
extern "C" void kernel_launch(void* const* d_in, const int* in_sizes, int n_in,
                              void* d_out, int out_size) {
    const float* x    = (const float*)d_in[0];
    const int*   src  = (const int*)d_in[1];
    const int*   dst  = (const int*)d_in[2];
    const float* w    = (const float*)d_in[3];
    const float* Wn   = (const float*)d_in[4];
    const float* Ws   = (const float*)d_in[5];
    const float* bias = (const float*)d_in[6];
    float* out = (float*)d_out;

    const int n = in_sizes[0] / D;   // nodes
    const int E = in_sizes[3];       // edges (weight count is dtype-independent)
    const int blk = 256;

    zero_cnt_kernel<<<(n + blk - 1) / blk, blk>>>(src, n);
    hist_kernel<<<(E + blk - 1) / blk, blk>>>(dst, E);
    scan_kernel<<<1, 1024>>>(n, E);
    {
        int nt = (E + 1) / 2;
        scatter_kernel<<<(nt + blk - 1) / blk, blk>>>(src, dst, w, E);
    }
    {
        int warps_per_blk = blk / 32;
        int grid = (n + warps_per_blk - 1) / warps_per_blk;
        agg_kernel<<<grid, blk>>>(x, n);
    }
    {
        size_t smem = 2ull * 128 * RSTR * sizeof(float);  // 67,584 B
        cudaFuncSetAttribute(gemm_kernel,
                             cudaFuncAttributeMaxDynamicSharedMemorySize,
                             (int)smem);
        int grid = (n + BM - 1) / BM;
        gemm_kernel<<<grid, 256, smem>>>(x, Wn, Ws, bias, out, n);
    }
}